// round 15
// baseline (speedup 1.0000x reference)
#include <cuda_runtime.h>
#include <math.h>

#define BB 256
#define IND 512
#define OUTD 512
#define ED 256
#define DELTA_C 0.1f
#define LN_EPS_C 1e-5f

typedef unsigned long long u64;
typedef unsigned int u32;

// Scratch (device globals — no allocation allowed)
__device__ float4 g_WM[IND * (OUTD / 2)];  // (w_lo, w_hi, m_lo, m_hi)

// ---- packed f32x2 helpers (sm_100+; only add/mul/fma exist packed) ----
__device__ __forceinline__ u64 pack2(float lo, float hi) {
    u64 r; asm("mov.b64 %0, {%1,%2};" : "=l"(r) : "f"(lo), "f"(hi)); return r;
}
#define FMA2(d,a,b,c) asm("fma.rn.f32x2 %0,%1,%2,%3;" : "=l"(d) : "l"(a),"l"(b),"l"(c))
#define MUL2(d,a,b)   asm("mul.rn.f32x2 %0,%1,%2;"    : "=l"(d) : "l"(a),"l"(b))
#define UNPACK2(lo,hi,v) asm("mov.b64 {%0,%1}, %2;" : "=f"(lo),"=f"(hi) : "l"(v))

__device__ __forceinline__ u32 smem_u32(const void* p) {
    u32 a;
    asm("{ .reg .u64 t; cvta.to.shared.u64 t, %1; cvt.u32.u64 %0, t; }"
        : "=r"(a) : "l"(p));
    return a;
}

#define CLUSTER_SYNC() do {                                         \
    asm volatile("barrier.cluster.arrive.aligned;" ::: "memory");   \
    asm volatile("barrier.cluster.wait.aligned;" ::: "memory");     \
} while (0)

// ============================================================
// Kernel 1 (fused front end): scores GEMM + cluster LayerNorm +
// sigmoid -> g_WM.  grid 128 = 16 clusters x 8 CTAs, block 128.
// Cluster = one i-tile (32 rows); CTA rank = o-tile (64 cols).
// GEMM reads AW/PE directly (transpose-on-stage, R12-measured OK).
// LN stats: shfl partials over 64-o per CTA -> DSMEM all-gather of
// 8 ranks' partials -> full-o mu/rsigma per i.  Epilogue reads the
// W tile from global (transposed via smem) and writes g_WM.
// ============================================================
__global__ __launch_bounds__(128) __cluster_dims__(8, 1, 1)
void kernel_front(
    const float* __restrict__ PE, const float* __restrict__ AW,
    const float* __restrict__ AB, const float* __restrict__ LG,
    const float* __restrict__ LB, const float* __restrict__ W) {
    __shared__ float awb[2][32][68];   // [buf][e][o_local]
    __shared__ u64 peb[2][32][34];     // [buf][e][i_local] dup
    __shared__ float wt[64][33];       // W tile transposed-on-read
    __shared__ float lnpart[32][2];    // per-CTA partial (sum, sum2) per i
    __shared__ float mus[32], rss[32];

    const int tid = threadIdx.x;
    const int to = tid & 15;
    const int ti = tid >> 4;
    const int bx = blockIdx.x;
    const int o0 = (bx & 7) * 64;      // cluster rank = bx & 7
    const int i0 = (bx >> 3) * 32;

    // staging maps (R12)
    const int a_ol = tid >> 3;          // [0,16)
    const int a_ec = (tid & 7) * 4;
    const int p_il = tid >> 2;          // [0,32)
    const int p_ec = (tid & 3) * 8;

    u64 acc[4][2];
    const u64 z = pack2(0.f, 0.f);
#pragma unroll
    for (int ii = 0; ii < 4; ii++) { acc[ii][0] = z; acc[ii][1] = z; }

    float4 qa[4];
    float4 qp[2];

    auto LDGC = [&](int e0) {
#pragma unroll
        for (int k = 0; k < 4; k++)
            qa[k] = *(const float4*)(AW + (o0 + a_ol + 16 * k) * ED + e0 + a_ec);
#pragma unroll
        for (int k = 0; k < 2; k++)
            qp[k] = *(const float4*)(PE + (i0 + p_il) * ED + e0 + p_ec + 4 * k);
    };
    auto STSC = [&](int buf) {
#pragma unroll
        for (int k = 0; k < 4; k++) {
            awb[buf][a_ec + 0][a_ol + 16 * k] = qa[k].x;
            awb[buf][a_ec + 1][a_ol + 16 * k] = qa[k].y;
            awb[buf][a_ec + 2][a_ol + 16 * k] = qa[k].z;
            awb[buf][a_ec + 3][a_ol + 16 * k] = qa[k].w;
        }
#pragma unroll
        for (int k = 0; k < 2; k++) {
            peb[buf][p_ec + 4 * k + 0][p_il] = pack2(qp[k].x, qp[k].x);
            peb[buf][p_ec + 4 * k + 1][p_il] = pack2(qp[k].y, qp[k].y);
            peb[buf][p_ec + 4 * k + 2][p_il] = pack2(qp[k].z, qp[k].z);
            peb[buf][p_ec + 4 * k + 3][p_il] = pack2(qp[k].w, qp[k].w);
        }
    };
    auto COMPUTE = [&](int buf) {
#pragma unroll 4
        for (int e = 0; e < 32; e++) {
            ulonglong2 a = *(const ulonglong2*)&awb[buf][e][4 * to];
            ulonglong2 p01 = *(const ulonglong2*)&peb[buf][e][4 * ti];
            ulonglong2 p23 = *(const ulonglong2*)&peb[buf][e][4 * ti + 2];
            FMA2(acc[0][0], p01.x, a.x, acc[0][0]);
            FMA2(acc[0][1], p01.x, a.y, acc[0][1]);
            FMA2(acc[1][0], p01.y, a.x, acc[1][0]);
            FMA2(acc[1][1], p01.y, a.y, acc[1][1]);
            FMA2(acc[2][0], p23.x, a.x, acc[2][0]);
            FMA2(acc[2][1], p23.x, a.y, acc[2][1]);
            FMA2(acc[3][0], p23.y, a.x, acc[3][0]);
            FMA2(acc[3][1], p23.y, a.y, acc[3][1]);
        }
    };

    LDGC(0);
    STSC(0);
    __syncthreads();
#pragma unroll 1
    for (int c = 0; c < 8; c++) {
        if (c < 7) LDGC(32 * (c + 1));
        COMPUTE(c & 1);
        if (c < 7) {
            STSC((c + 1) & 1);
            __syncthreads();
        }
    }

    // scores (with bias) into registers: s[ii][k], o = o0 + 4*to + k
    float4 bb = *(const float4*)(AB + o0 + 4 * to);
    float s[4][4];
#pragma unroll
    for (int ii = 0; ii < 4; ii++) {
        UNPACK2(s[ii][0], s[ii][1], acc[ii][0]);
        UNPACK2(s[ii][2], s[ii][3], acc[ii][1]);
        s[ii][0] += bb.x; s[ii][1] += bb.y;
        s[ii][2] += bb.z; s[ii][3] += bb.w;
    }

    // per-CTA partial LN sums over 64 o, reduced across the 16 'to' lanes
    float ps[4], ps2[4];
#pragma unroll
    for (int ii = 0; ii < 4; ii++) {
        ps[ii]  = s[ii][0] + s[ii][1] + s[ii][2] + s[ii][3];
        ps2[ii] = s[ii][0] * s[ii][0] + s[ii][1] * s[ii][1]
                + s[ii][2] * s[ii][2] + s[ii][3] * s[ii][3];
    }
#pragma unroll
    for (int off = 8; off > 0; off >>= 1) {
#pragma unroll
        for (int ii = 0; ii < 4; ii++) {
            ps[ii]  += __shfl_xor_sync(0xffffffffu, ps[ii],  off);
            ps2[ii] += __shfl_xor_sync(0xffffffffu, ps2[ii], off);
        }
    }
    if (to == 0) {
#pragma unroll
        for (int ii = 0; ii < 4; ii++) {
            lnpart[4 * ti + ii][0] = ps[ii];
            lnpart[4 * ti + ii][1] = ps2[ii];
        }
    }

    // stage W tile (64 o-rows x 32 i-cols) while waiting for the cluster
    {
        int row = tid >> 1;
        int cb = (tid & 1) * 16;
        const float* wr = W + (o0 + row) * IND + i0 + cb;
#pragma unroll
        for (int k = 0; k < 4; k++) {
            float4 v4 = *(const float4*)(wr + 4 * k);
            wt[row][cb + 4 * k + 0] = v4.x;
            wt[row][cb + 4 * k + 1] = v4.y;
            wt[row][cb + 4 * k + 2] = v4.z;
            wt[row][cb + 4 * k + 3] = v4.w;
        }
    }

    CLUSTER_SYNC();   // all ranks' lnpart visible

    // all-gather LN partials from 8 ranks via DSMEM
    if (tid < 32) {
        u32 myaddr = smem_u32(&lnpart[tid][0]);
        float su = 0.f, sq = 0.f;
#pragma unroll
        for (int r = 0; r < 8; r++) {
            u32 rem;
            asm("mapa.shared::cluster.u32 %0, %1, %2;"
                : "=r"(rem) : "r"(myaddr), "r"(r));
            float a, b;
            asm volatile("ld.shared::cluster.f32 %0, [%1];"
                         : "=f"(a) : "r"(rem));
            asm volatile("ld.shared::cluster.f32 %0, [%1+4];"
                         : "=f"(b) : "r"(rem));
            su += a; sq += b;
        }
        float mu = su * (1.f / OUTD);
        float var = sq * (1.f / OUTD) - mu * mu;
        mus[tid] = mu;
        rss[tid] = rsqrtf(var + LN_EPS_C);
    }

    CLUSTER_SYNC();   // reads done (no early exit); mus/rss visible block-wide

    // epilogue: LN -> sigmoid -> g_WM
    float4 lg4 = *(const float4*)(LG + o0 + 4 * to);
    float4 lb4 = *(const float4*)(LB + o0 + 4 * to);
    const int pbase = o0 / 2 + 2 * to;
#pragma unroll
    for (int ii = 0; ii < 4; ii++) {
        const int il = 4 * ti + ii;
        const int i = i0 + il;
        float mu = mus[il], rs = rss[il];
        float w0 = wt[4 * to + 0][il];
        float w1 = wt[4 * to + 1][il];
        float w2 = wt[4 * to + 2][il];
        float w3 = wt[4 * to + 3][il];
        float v0 = (s[ii][0] - mu) * rs * lg4.x + lb4.x;
        float v1 = (s[ii][1] - mu) * rs * lg4.y + lb4.y;
        float v2 = (s[ii][2] - mu) * rs * lg4.z + lb4.z;
        float v3 = (s[ii][3] - mu) * rs * lg4.w + lb4.w;
        float g0 = 1.f / (1.f + __expf(-v0));
        float g1 = 1.f / (1.f + __expf(-v1));
        float g2 = 1.f / (1.f + __expf(-v2));
        float g3 = 1.f / (1.f + __expf(-v3));
        float4 q0, q1;
        q0.x = w0; q0.y = w1;
        q0.z = fabsf(w0) * g0; q0.w = fabsf(w1) * g1;
        q1.x = w2; q1.y = w3;
        q1.z = fabsf(w2) * g2; q1.w = fabsf(w3) * g3;
        g_WM[i * (OUTD / 2) + pbase] = q0;
        g_WM[i * (OUTD / 2) + pbase + 1] = q1;
    }
}

// ============================================================
// Kernel 2 (main): out[b,o] = x@Wt + 0.1*(max_i t*M - sum_i t*M)
// (FROZEN from R12/R13 — measured 20.9us)
// ============================================================
#define MAIN_SMEM (64 * 1024)
#define XT_B_BYTES 8192           // 512 i * 16 B
#define WM_ROW_BYTES 4096         // 256 pairs * 16 B

__global__ __launch_bounds__(256, 2) void kernel_main(
    const float* __restrict__ X, float* __restrict__ out) {
    extern __shared__ char smem_raw[];
    ulonglong2 (*xt)[IND] = (ulonglong2 (*)[IND])smem_raw;  // [4][512] = 32KB
    float* red = (float*)smem_raw;                          // 64KB after sync

    const int tid = threadIdx.x;
    const int to = tid & 15;
    const int hs = tid >> 4;
    const int b0 = blockIdx.y * 4;
    const int ib = hs * 32;

#pragma unroll
    for (int r = 0; r < 2; r++) {
        int idx = tid + r * 256;
        int b = idx >> 7, i4 = idx & 127;
        float4 xv = *(const float4*)(X + (b0 + b) * IND + i4 * 4);
        float xs[4] = {xv.x, xv.y, xv.z, xv.w};
#pragma unroll
        for (int k = 0; k < 4; k++) {
            float x1 = xs[k];
            float t1 = x1 * fabsf(x1);
            xt[b][i4 * 4 + k] = make_ulonglong2(pack2(x1, x1), pack2(t1, t1));
        }
    }
    __syncthreads();

    u64 c[4][4];
    float mxl[4][4], mxh[4][4];
    const u64 z = pack2(0.f, 0.f);
    const u64 n01 = pack2(-DELTA_C, -DELTA_C);
#pragma unroll
    for (int b = 0; b < 4; b++)
#pragma unroll
        for (int j = 0; j < 4; j++) {
            c[b][j] = z;
            mxl[b][j] = -INFINITY;
            mxh[b][j] = -INFINITY;
        }

    const char* xp = smem_raw + ib * 16;
    const char* wp = (const char*)g_WM +
                     ((u64)ib * 256 + blockIdx.x * 64 + to) * 16;

    ulonglong2 qa[4], na[4];

#define LOADG(q, base) do {                                          \
        (q)[0] = *(const ulonglong2*)((base));                       \
        (q)[1] = *(const ulonglong2*)((base) + 256);                 \
        (q)[2] = *(const ulonglong2*)((base) + 512);                 \
        (q)[3] = *(const ulonglong2*)((base) + 768);                 \
    } while (0)

#define COMPG(q, xb) do {                                            \
        _Pragma("unroll")                                            \
        for (int b = 0; b < 4; b++) {                                \
            ulonglong2 v = *(const ulonglong2*)((xb) + b * XT_B_BYTES); \
            _Pragma("unroll")                                        \
            for (int j = 0; j < 4; j++) {                            \
                FMA2(c[b][j], v.x, (q)[j].x, c[b][j]);               \
                u64 p; MUL2(p, v.y, (q)[j].y);                       \
                FMA2(c[b][j], p, n01, c[b][j]);                      \
                float plo, phi; UNPACK2(plo, phi, p);                \
                mxl[b][j] = fmaxf(mxl[b][j], plo);                   \
                mxh[b][j] = fmaxf(mxh[b][j], phi);                   \
            }                                                        \
        }                                                            \
    } while (0)

    LOADG(qa, wp);
#pragma unroll 1
    for (int g = 0; g < 16; g++) {
        LOADG(na, wp + 1 * WM_ROW_BYTES);
        COMPG(qa, xp);
        if (g < 15) LOADG(qa, wp + 2 * WM_ROW_BYTES);
        COMPG(na, xp + 16);
        wp += 2 * WM_ROW_BYTES;
        xp += 32;
    }
#undef LOADG
#undef COMPG

    __syncthreads();

#define RIDX(k, b, j, s, t) ((((((k) * 4 + (b)) * 4 + (j)) * 16 + (s)) * 16) + (t))
#pragma unroll
    for (int b = 0; b < 4; b++)
#pragma unroll
        for (int j = 0; j < 4; j++) {
            float clo, chi;
            UNPACK2(clo, chi, c[b][j]);
            red[RIDX(0, b, j, hs, to)] = clo;
            red[RIDX(1, b, j, hs, to)] = chi;
            red[RIDX(2, b, j, hs, to)] = mxl[b][j];
            red[RIDX(3, b, j, hs, to)] = mxh[b][j];
        }
    __syncthreads();

    {
        const int b2 = tid >> 6;
        const int pl = tid & 63;
        const int j2 = pl >> 4;
        const int to2 = pl & 15;
        float slo = 0.f, shi = 0.f, Mlo = -INFINITY, Mhi = -INFINITY;
#pragma unroll
        for (int s = 0; s < 16; s++) {
            slo += red[RIDX(0, b2, j2, s, to2)];
            shi += red[RIDX(1, b2, j2, s, to2)];
            Mlo = fmaxf(Mlo, red[RIDX(2, b2, j2, s, to2)]);
            Mhi = fmaxf(Mhi, red[RIDX(3, b2, j2, s, to2)]);
        }
        float2 r;
        r.x = slo + DELTA_C * Mlo;
        r.y = shi + DELTA_C * Mhi;
        *(float2*)(out + (b0 + b2) * OUTD + blockIdx.x * 128 + j2 * 32 + to2 * 2) = r;
    }
#undef RIDX
}

// ============================================================
extern "C" void kernel_launch(void* const* d_in, const int* in_sizes, int n_in,
                              void* d_out, int out_size) {
    const float* x  = (const float*)d_in[0];
    const float* w  = (const float*)d_in[1];
    const float* pe = (const float*)d_in[2];
    const float* aw = (const float*)d_in[3];
    const float* ab = (const float*)d_in[4];
    const float* lg = (const float*)d_in[5];
    const float* lb = (const float*)d_in[6];
    float* out = (float*)d_out;

    cudaFuncSetAttribute(kernel_main,
                         cudaFuncAttributeMaxDynamicSharedMemorySize,
                         MAIN_SMEM);

    kernel_front<<<128, 128>>>(pe, aw, ab, lg, lb, w);
    kernel_main<<<dim3(4, 64), 256, MAIN_SMEM>>>(x, out);
}